// round 6
// baseline (speedup 1.0000x reference)
#include <cuda_runtime.h>
#include <cstdint>

#define S_LEN   2048
#define D_K     64
#define BH      64
#define MT      64
#define NT      64
#define PADQ    72   // permuted+swizzled A layouts (Q, Ps): LDS.64 conflict-free
#define PADP    72
#define PADK    68   // raw K: scalar B-reads conflict-free
#define PADV    72   // raw V: scalar B-reads conflict-free
#define THREADS 256
#define NBLOCKS (BH * (S_LEN / MT))   // 2048

__device__ float g_linv[BH * S_LEN];
__device__ int   g_queue[NBLOCKS];
__device__ int   g_push;
__device__ int   g_ticket;

__device__ __forceinline__ uint32_t f2tf32(float x) {
    uint32_t r;
    asm("cvt.rna.tf32.f32 %0, %1;" : "=r"(r) : "f"(x));
    return r;
}

__device__ __forceinline__ void mma_tf32(float c[4],
                                         uint32_t a0, uint32_t a1, uint32_t a2, uint32_t a3,
                                         uint32_t b0, uint32_t b1) {
    asm volatile(
        "mma.sync.aligned.m16n8k8.row.col.f32.tf32.tf32.f32 "
        "{%0,%1,%2,%3},{%4,%5,%6,%7},{%8,%9},{%0,%1,%2,%3};"
        : "+f"(c[0]), "+f"(c[1]), "+f"(c[2]), "+f"(c[3])
        : "r"(a0), "r"(a1), "r"(a2), "r"(a3), "r"(b0), "r"(b1));
}

__device__ __forceinline__ void cp_async16(uint32_t s, const void* g) {
    asm volatile("cp.async.cg.shared.global [%0], [%1], 16;" :: "r"(s), "l"(g));
}
#define CP_COMMIT() asm volatile("cp.async.commit_group;")
#define CP_WAIT1()  asm volatile("cp.async.wait_group 1;")
#define CP_WAIT0()  asm volatile("cp.async.wait_group 0;")

__device__ __forceinline__ void cp_tile(uint32_t dst_base, const float* __restrict__ src,
                                        int tid, int pad) {
    #pragma unroll
    for (int i = 0; i < 4; i++) {
        int idx = i * THREADS + tid;
        int row = idx >> 4;
        int c4  = (idx & 15) << 2;
        cp_async16(dst_base + (row * pad + c4) * 4, src + idx * 4);
    }
}

// Q tile: scale folded, tf32, stored in permuted-k layout:
// within each 8-col block, col c sits at position (2*(c&3) + ((c&4)>>2)) ^ key(row),
// key(row) = (row&4)>>1.  Makes cols {t, t+4} adjacent -> LDS.64 A-gathers.
__device__ __forceinline__ void load_q(float* Qs, const float* __restrict__ Qg, int tid) {
    const float4* q4 = (const float4*)Qg;
    #pragma unroll
    for (int i = 0; i < 4; i++) {
        int idx = i * THREADS + tid;
        float4 v = q4[idx];
        int row = idx >> 4;
        int c4  = (idx & 15) << 2;
        int blk  = c4 >> 3;
        int half = (c4 & 4) >> 2;          // cols c4..c4+3 are block-half 0 or 1
        int key  = (row & 4) >> 1;
        float* d = Qs + row * PADQ + blk * 8;
        d[(0 + half) ^ key] = __uint_as_float(f2tf32(v.x * 0.125f));
        d[(2 + half) ^ key] = __uint_as_float(f2tf32(v.y * 0.125f));
        d[(4 + half) ^ key] = __uint_as_float(f2tf32(v.z * 0.125f));
        d[(6 + half) ^ key] = __uint_as_float(f2tf32(v.w * 0.125f));
    }
}

__global__ __launch_bounds__(THREADS, 3)
void sdpa_fused(const float* __restrict__ Q, const float* __restrict__ K,
                const float* __restrict__ V, const int* __restrict__ mask,
                float* __restrict__ out) {
    extern __shared__ float sm[];
    float* Qs  = sm;                         // 64 x PADQ (permuted)
    float* Ks  = Qs + MT * PADQ;             // 64 x PADK (raw)
    float* Vs  = Ks + MT * PADK;             // 64 x PADV (raw)
    float* Ps  = Vs + MT * PADV;             // 64 x PADP (permuted)
    float* red = Ps + MT * PADP;             // 64 x 4
    float* liS = red + 64 * 4;               // 64
    __shared__ int s_strip;

    const uint32_t base = (uint32_t)__cvta_generic_to_shared(sm);
    const uint32_t KsA = base + MT * PADQ * 4;
    const uint32_t VsA = KsA + MT * PADK * 4;

    const int bh  = blockIdx.y;
    const int q0  = blockIdx.x * MT;
    const int myid = blockIdx.y * gridDim.x + blockIdx.x;
    const int tid = threadIdx.x;
    const int lane = tid & 31, wid = tid >> 5;
    const int g = lane >> 2, tig = lane & 3;
    const int wm = wid & 1, wn = wid >> 1;

    const int key   = (g & 4) >> 1;              // row-swizzle key (rows ≡ g mod 16)
    const int axoff = (2 * tig) ^ key;           // A-pair word offset within 8-block
    const int pos0  = (2 * ((2 * tig) & 3) + (((2 * tig) & 4) >> 2));  // perm pos of col 2tig
    const int st0   = pos0 ^ key;                // Ps store offsets
    const int st1   = (pos0 + 2) ^ key;

    const float* Qg = Q + ((size_t)bh * S_LEN + q0) * D_K;
    const float* Kg = K + (size_t)bh * S_LEN * D_K;
    const float* Vg = V + (size_t)bh * S_LEN * D_K;
    const int*   Mg = mask + (size_t)bh * S_LEN * S_LEN;
    float* ctx  = out + (size_t)bh * S_LEN * D_K;
    float* attn_base = out + (size_t)BH * S_LEN * D_K;
    float* attn = attn_base + (size_t)bh * S_LEN * S_LEN;

    load_q(Qs, Qg, tid);
    cp_tile(KsA, Kg, tid, PADK);           // K(0)
    CP_COMMIT();

    float o[2][2][4] = {};
    float lp[2][2] = {};

    for (int kt = 0; kt < S_LEN; kt += NT) {
        CP_WAIT0();
        __syncthreads();                   // K visible; prev PV done

        cp_tile(VsA, Vg + (size_t)kt * D_K, tid, PADV);   // V(t)
        CP_COMMIT();

        // mask prefetch (overlaps QK)
        int2 mreg[2][2][2];
        #pragma unroll
        for (int mb = 0; mb < 2; mb++) {
            int row = wm * 32 + mb * 16 + g;
            #pragma unroll
            for (int nf = 0; nf < 2; nf++) {
                int col = wn * 16 + nf * 8 + 2 * tig;
                mreg[mb][nf][0] = *(const int2*)(Mg + (size_t)(q0 + row)     * S_LEN + kt + col);
                mreg[mb][nf][1] = *(const int2*)(Mg + (size_t)(q0 + row + 8) * S_LEN + kt + col);
            }
        }

        // ---- S = Q K^T (A via LDS.64 from permuted Qs) ----
        float acc[2][2][4] = {};
        #pragma unroll
        for (int j = 0; j < 8; j++) {
            int k0 = j * 8;
            uint32_t a[2][4];
            #pragma unroll
            for (int mb = 0; mb < 2; mb++) {
                int r0 = wm * 32 + mb * 16 + g;
                float2 a02 = *(const float2*)&Qs[r0       * PADQ + k0 + axoff];
                float2 a13 = *(const float2*)&Qs[(r0 + 8) * PADQ + k0 + axoff];
                a[mb][0] = __float_as_uint(a02.x);
                a[mb][1] = __float_as_uint(a13.x);
                a[mb][2] = __float_as_uint(a02.y);
                a[mb][3] = __float_as_uint(a13.y);
            }
            #pragma unroll
            for (int nf = 0; nf < 2; nf++) {
                int nc = wn * 16 + nf * 8 + g;
                uint32_t b0 = f2tf32(Ks[nc * PADK + k0 + tig]);
                uint32_t b1 = f2tf32(Ks[nc * PADK + k0 + tig + 4]);
                #pragma unroll
                for (int mb = 0; mb < 2; mb++)
                    mma_tf32(acc[mb][nf], a[mb][0], a[mb][1], a[mb][2], a[mb][3], b0, b1);
            }
        }
        __syncthreads();                   // done reading Ks

        // prefetch K(t+1)
        const float* Knext = (kt + NT < S_LEN) ? Kg + (size_t)(kt + NT) * D_K : Kg;
        cp_tile(KsA, Knext, tid, PADK);
        CP_COMMIT();

        // ---- p = mask*exp(s): write attn, stage P permuted, sum rows ----
        #pragma unroll
        for (int mb = 0; mb < 2; mb++) {
            int row = wm * 32 + mb * 16 + g;
            #pragma unroll
            for (int nf = 0; nf < 2; nf++) {
                int col = wn * 16 + nf * 8 + 2 * tig;
                int2 m0 = mreg[mb][nf][0];
                int2 m1 = mreg[mb][nf][1];
                float p00 = m0.x ? __expf(acc[mb][nf][0]) : 0.f;
                float p01 = m0.y ? __expf(acc[mb][nf][1]) : 0.f;
                float p10 = m1.x ? __expf(acc[mb][nf][2]) : 0.f;
                float p11 = m1.y ? __expf(acc[mb][nf][3]) : 0.f;
                lp[mb][0] += p00 + p01;
                lp[mb][1] += p10 + p11;
                *(float2*)(attn + (size_t)(q0 + row)     * S_LEN + kt + col) = make_float2(p00, p01);
                *(float2*)(attn + (size_t)(q0 + row + 8) * S_LEN + kt + col) = make_float2(p10, p11);
                int pb = (wn * 2 + nf) * 8;           // 8-block base in Ps row
                float* pr0 = Ps + row       * PADP + pb;
                float* pr1 = Ps + (row + 8) * PADP + pb;
                pr0[st0] = __uint_as_float(f2tf32(p00));
                pr0[st1] = __uint_as_float(f2tf32(p01));
                pr1[st0] = __uint_as_float(f2tf32(p10));
                pr1[st1] = __uint_as_float(f2tf32(p11));
            }
        }

        CP_WAIT1();                        // V(t) done
        __syncthreads();                   // Ps + Vs visible

        // ---- O += P V (A via LDS.64 from permuted Ps) ----
        #pragma unroll
        for (int j = 0; j < 8; j++) {
            int kk = j * 8;
            uint32_t a[2][4];
            #pragma unroll
            for (int mb = 0; mb < 2; mb++) {
                int r0 = wm * 32 + mb * 16 + g;
                float2 a02 = *(const float2*)&Ps[r0       * PADP + kk + axoff];
                float2 a13 = *(const float2*)&Ps[(r0 + 8) * PADP + kk + axoff];
                a[mb][0] = __float_as_uint(a02.x);
                a[mb][1] = __float_as_uint(a13.x);
                a[mb][2] = __float_as_uint(a02.y);
                a[mb][3] = __float_as_uint(a13.y);
            }
            #pragma unroll
            for (int nf = 0; nf < 2; nf++) {
                int dc = wn * 16 + nf * 8 + g;
                uint32_t b0 = f2tf32(Vs[(kk + tig)     * PADV + dc]);
                uint32_t b1 = f2tf32(Vs[(kk + tig + 4) * PADV + dc]);
                #pragma unroll
                for (int mb = 0; mb < 2; mb++)
                    mma_tf32(o[mb][nf], a[mb][0], a[mb][1], a[mb][2], a[mb][3], b0, b1);
            }
        }
    }

    // ---- row sums -> l_inv ----
    #pragma unroll
    for (int mb = 0; mb < 2; mb++)
        #pragma unroll
        for (int h = 0; h < 2; h++) {
            float s = lp[mb][h];
            s += __shfl_xor_sync(0xffffffffu, s, 1);
            s += __shfl_xor_sync(0xffffffffu, s, 2);
            lp[mb][h] = s;
        }
    if (tig == 0)
        #pragma unroll
        for (int mb = 0; mb < 2; mb++)
            #pragma unroll
            for (int h = 0; h < 2; h++)
                red[(wm * 32 + mb * 16 + g + h * 8) * 4 + wn] = lp[mb][h];
    __syncthreads();
    if (tid < 64) {
        float li = 1.f / (red[tid * 4] + red[tid * 4 + 1] + red[tid * 4 + 2] + red[tid * 4 + 3]);
        liS[tid] = li;
        g_linv[(size_t)bh * S_LEN + q0 + tid] = li;
    }
    __syncthreads();

    // ---- write context ----
    #pragma unroll
    for (int mb = 0; mb < 2; mb++) {
        int row = wm * 32 + mb * 16 + g;
        float li0 = liS[row], li1 = liS[row + 8];
        #pragma unroll
        for (int nf = 0; nf < 2; nf++) {
            int col = wn * 16 + nf * 8 + 2 * tig;
            *(float2*)(ctx + (size_t)(q0 + row)     * D_K + col) =
                make_float2(o[mb][nf][0] * li0, o[mb][nf][1] * li0);
            *(float2*)(ctx + (size_t)(q0 + row + 8) * D_K + col) =
                make_float2(o[mb][nf][2] * li1, o[mb][nf][3] * li1);
        }
    }

    // ---- produce/consume: normalize one already-produced strip (L2-hot) ----
    __threadfence();
    __syncthreads();
    if (tid == 0) {
        int idx = atomicAdd(&g_push, 1);
        asm volatile("st.release.gpu.global.s32 [%0], %1;"
                     :: "l"(g_queue + idx), "r"(myid) : "memory");
        int t = atomicAdd(&g_ticket, 1);
        int s;
        while (true) {
            asm volatile("ld.acquire.gpu.global.s32 %0, [%1];"
                         : "=r"(s) : "l"(g_queue + t) : "memory");
            if (s >= 0) break;
            __nanosleep(64);
        }
        s_strip = s;
    }
    __syncthreads();

    const int sid  = s_strip;
    const int sbh  = sid >> 5;
    const int sq0  = (sid & 31) * MT;
    float* sattn = attn_base + (size_t)sbh * S_LEN * S_LEN + (size_t)sq0 * S_LEN;
    if (tid < 64) liS[tid] = g_linv[(size_t)sbh * S_LEN + sq0 + tid];
    __syncthreads();

    #pragma unroll 4
    for (int i = tid; i < MT * (S_LEN / 4); i += THREADS) {
        float li = liS[i >> 9];
        float4* p = (float4*)sattn + i;
        float4 v = *p;
        v.x *= li; v.y *= li; v.z *= li; v.w *= li;
        *p = v;
    }
}

extern "C" void kernel_launch(void* const* d_in, const int* in_sizes, int n_in,
                              void* d_out, int out_size) {
    const float* Q    = (const float*)d_in[0];
    const float* K    = (const float*)d_in[1];
    const float* V    = (const float*)d_in[2];
    const int*   mask = (const int*)d_in[3];
    float* out = (float*)d_out;

    void* addr;
    cudaGetSymbolAddress(&addr, g_queue);
    cudaMemsetAsync(addr, 0xFF, sizeof(int) * NBLOCKS);
    cudaGetSymbolAddress(&addr, g_push);
    cudaMemsetAsync(addr, 0, sizeof(int));
    cudaGetSymbolAddress(&addr, g_ticket);
    cudaMemsetAsync(addr, 0, sizeof(int));

    const int smem = (MT * PADQ + MT * PADK + MT * PADV + MT * PADP + 64 * 4 + 64) * sizeof(float);
    cudaFuncSetAttribute(sdpa_fused, cudaFuncAttributeMaxDynamicSharedMemorySize, smem);

    dim3 grid(S_LEN / MT, BH);
    sdpa_fused<<<grid, THREADS, smem>>>(Q, K, V, mask, out);
}

// round 7
// speedup vs baseline: 1.0059x; 1.0059x over previous
#include <cuda_runtime.h>
#include <cstdint>

#define S_LEN   2048
#define D_K     64
#define BH      64
#define MT      128
#define NT      64
#define PADK    68   // (4x+tig) bank pattern -> conflict-free
#define PADV    72   // (8tig+g) bank pattern -> conflict-free
#define THREADS 256
#define NBLOCKS (BH * (S_LEN / MT))   // 1024

__device__ float g_linv[BH * S_LEN];
__device__ int   g_queue[NBLOCKS];
__device__ int   g_push;
__device__ int   g_ticket;

__device__ __forceinline__ uint32_t f2tf32(float x) {
    uint32_t r;
    asm("cvt.rna.tf32.f32 %0, %1;" : "=r"(r) : "f"(x));
    return r;
}

__device__ __forceinline__ void mma_tf32(float c[4],
                                         uint32_t a0, uint32_t a1, uint32_t a2, uint32_t a3,
                                         uint32_t b0, uint32_t b1) {
    asm volatile(
        "mma.sync.aligned.m16n8k8.row.col.f32.tf32.tf32.f32 "
        "{%0,%1,%2,%3},{%4,%5,%6,%7},{%8,%9},{%0,%1,%2,%3};"
        : "+f"(c[0]), "+f"(c[1]), "+f"(c[2]), "+f"(c[3])
        : "r"(a0), "r"(a1), "r"(a2), "r"(a3), "r"(b0), "r"(b1));
}

__device__ __forceinline__ void cp_async16(uint32_t s, const void* g) {
    asm volatile("cp.async.cg.shared.global [%0], [%1], 16;" :: "r"(s), "l"(g));
}
#define CP_COMMIT() asm volatile("cp.async.commit_group;")
#define CP_WAIT1()  asm volatile("cp.async.wait_group 1;")
#define CP_WAIT0()  asm volatile("cp.async.wait_group 0;")

// one 64x64 fp32 tile (K or V) -> padded smem
__device__ __forceinline__ void cp_tile(uint32_t dst_base, const float* __restrict__ src,
                                        int tid, int pad) {
    #pragma unroll
    for (int i = 0; i < 4; i++) {
        int idx = i * THREADS + tid;
        int row = idx >> 4;
        int c4  = (idx & 15) << 2;
        cp_async16(dst_base + (row * pad + c4) * 4, src + idx * 4);
    }
}

// Q tile 128x64: scale folded, tf32
__device__ __forceinline__ void load_q(float* Qs, const float* __restrict__ Qg, int tid) {
    const float4* q4 = (const float4*)Qg;
    #pragma unroll
    for (int i = 0; i < 8; i++) {
        int idx = i * THREADS + tid;          // 2048 float4
        float4 v = q4[idx];
        int row = idx >> 4;
        int c4  = (idx & 15) << 2;
        float* d = Qs + row * PADK + c4;
        d[0] = __uint_as_float(f2tf32(v.x * 0.125f));
        d[1] = __uint_as_float(f2tf32(v.y * 0.125f));
        d[2] = __uint_as_float(f2tf32(v.z * 0.125f));
        d[3] = __uint_as_float(f2tf32(v.w * 0.125f));
    }
}

__global__ __launch_bounds__(THREADS, 2)
void sdpa_fused(const float* __restrict__ Q, const float* __restrict__ K,
                const float* __restrict__ V, const int* __restrict__ mask,
                float* __restrict__ out) {
    extern __shared__ float sm[];
    float* Qs  = sm;                         // 128 x PADK
    float* Ks  = Qs + MT * PADK;             // 64 x PADK
    float* Vs  = Ks + NT * PADK;             // 64 x PADV
    float* Ps  = Vs + NT * PADV;             // 128 x PADK
    float* red = Ps + MT * PADK;             // 128 x 2
    float* liS = red + MT * 2;               // 128
    __shared__ int s_strip;

    const uint32_t base = (uint32_t)__cvta_generic_to_shared(sm);
    const uint32_t KsA = base + MT * PADK * 4;
    const uint32_t VsA = KsA + NT * PADK * 4;

    const int bh  = blockIdx.y;
    const int q0  = blockIdx.x * MT;
    const int myid = blockIdx.y * gridDim.x + blockIdx.x;
    const int tid = threadIdx.x;
    const int lane = tid & 31, wid = tid >> 5;
    const int g = lane >> 2, tig = lane & 3;
    const int wm = wid & 3;                  // 4 warps in M (32 rows each)
    const int wn = wid >> 2;                 // 2 warps in N (32 cols each)

    const float* Qg = Q + ((size_t)bh * S_LEN + q0) * D_K;
    const float* Kg = K + (size_t)bh * S_LEN * D_K;
    const float* Vg = V + (size_t)bh * S_LEN * D_K;
    const int*   Mg = mask + (size_t)bh * S_LEN * S_LEN;
    float* ctx  = out + (size_t)bh * S_LEN * D_K;
    float* attn_base = out + (size_t)BH * S_LEN * D_K;
    float* attn = attn_base + (size_t)bh * S_LEN * S_LEN;

    load_q(Qs, Qg, tid);
    cp_tile(KsA, Kg, tid, PADK);           // K(0)
    CP_COMMIT();

    float o[2][4][4] = {};                 // [mb][nf][..]
    float lp[2][2] = {};

    for (int kt = 0; kt < S_LEN; kt += NT) {
        CP_WAIT0();                        // K(t) arrived
        __syncthreads();                   // K visible; prev PV done (Vs free)

        cp_tile(VsA, Vg + (size_t)kt * D_K, tid, PADV);   // V(t)
        CP_COMMIT();

        // mask prefetch (overlaps QK)
        int2 mreg[2][4][2];
        #pragma unroll
        for (int mb = 0; mb < 2; mb++) {
            int row = wm * 32 + mb * 16 + g;
            #pragma unroll
            for (int nf = 0; nf < 4; nf++) {
                int col = wn * 32 + nf * 8 + 2 * tig;
                mreg[mb][nf][0] = *(const int2*)(Mg + (size_t)(q0 + row)     * S_LEN + kt + col);
                mreg[mb][nf][1] = *(const int2*)(Mg + (size_t)(q0 + row + 8) * S_LEN + kt + col);
            }
        }

        // ---- S = Q K^T ----
        float acc[2][4][4] = {};
        #pragma unroll
        for (int j = 0; j < 8; j++) {
            int k0 = j * 8;
            uint32_t a[2][4];
            #pragma unroll
            for (int mb = 0; mb < 2; mb++) {
                int r0 = wm * 32 + mb * 16 + g;
                a[mb][0] = __float_as_uint(Qs[r0       * PADK + k0 + tig]);
                a[mb][1] = __float_as_uint(Qs[(r0 + 8) * PADK + k0 + tig]);
                a[mb][2] = __float_as_uint(Qs[r0       * PADK + k0 + tig + 4]);
                a[mb][3] = __float_as_uint(Qs[(r0 + 8) * PADK + k0 + tig + 4]);
            }
            #pragma unroll
            for (int nf = 0; nf < 4; nf++) {
                int nc = wn * 32 + nf * 8 + g;
                uint32_t b0 = f2tf32(Ks[nc * PADK + k0 + tig]);
                uint32_t b1 = f2tf32(Ks[nc * PADK + k0 + tig + 4]);
                #pragma unroll
                for (int mb = 0; mb < 2; mb++)
                    mma_tf32(acc[mb][nf], a[mb][0], a[mb][1], a[mb][2], a[mb][3], b0, b1);
            }
        }
        __syncthreads();                   // done reading Ks

        // prefetch K(t+1) (hidden behind exp/attn-write/PV)
        const float* Knext = (kt + NT < S_LEN) ? Kg + (size_t)(kt + NT) * D_K : Kg;
        cp_tile(KsA, Knext, tid, PADK);
        CP_COMMIT();

        // ---- p = mask*exp(s): write attn, stage P, sum rows ----
        #pragma unroll
        for (int mb = 0; mb < 2; mb++) {
            int row = wm * 32 + mb * 16 + g;
            #pragma unroll
            for (int nf = 0; nf < 4; nf++) {
                int col = wn * 32 + nf * 8 + 2 * tig;
                int2 m0 = mreg[mb][nf][0];
                int2 m1 = mreg[mb][nf][1];
                float p00 = m0.x ? __expf(acc[mb][nf][0]) : 0.f;
                float p01 = m0.y ? __expf(acc[mb][nf][1]) : 0.f;
                float p10 = m1.x ? __expf(acc[mb][nf][2]) : 0.f;
                float p11 = m1.y ? __expf(acc[mb][nf][3]) : 0.f;
                lp[mb][0] += p00 + p01;
                lp[mb][1] += p10 + p11;
                *(float2*)(attn + (size_t)(q0 + row)     * S_LEN + kt + col) = make_float2(p00, p01);
                *(float2*)(attn + (size_t)(q0 + row + 8) * S_LEN + kt + col) = make_float2(p10, p11);
                float2 s0, s1;
                s0.x = __uint_as_float(f2tf32(p00)); s0.y = __uint_as_float(f2tf32(p01));
                s1.x = __uint_as_float(f2tf32(p10)); s1.y = __uint_as_float(f2tf32(p11));
                *(float2*)&Ps[row       * PADK + col] = s0;
                *(float2*)&Ps[(row + 8) * PADK + col] = s1;
            }
        }

        CP_WAIT1();                        // V(t) done (K(t+1) in flight)
        __syncthreads();                   // Ps + Vs visible

        // ---- O += P V ----
        #pragma unroll
        for (int j = 0; j < 8; j++) {
            int kk = j * 8;
            uint32_t a[2][4];
            #pragma unroll
            for (int mb = 0; mb < 2; mb++) {
                int r0 = wm * 32 + mb * 16 + g;
                a[mb][0] = __float_as_uint(Ps[r0       * PADK + kk + tig]);
                a[mb][1] = __float_as_uint(Ps[(r0 + 8) * PADK + kk + tig]);
                a[mb][2] = __float_as_uint(Ps[r0       * PADK + kk + tig + 4]);
                a[mb][3] = __float_as_uint(Ps[(r0 + 8) * PADK + kk + tig + 4]);
            }
            #pragma unroll
            for (int nf = 0; nf < 4; nf++) {
                int dc = wn * 32 + nf * 8 + g;
                uint32_t b0 = f2tf32(Vs[(kk + tig)     * PADV + dc]);
                uint32_t b1 = f2tf32(Vs[(kk + tig + 4) * PADV + dc]);
                #pragma unroll
                for (int mb = 0; mb < 2; mb++)
                    mma_tf32(o[mb][nf], a[mb][0], a[mb][1], a[mb][2], a[mb][3], b0, b1);
            }
        }
    }

    // ---- row sums -> l_inv ----
    #pragma unroll
    for (int mb = 0; mb < 2; mb++)
        #pragma unroll
        for (int h = 0; h < 2; h++) {
            float s = lp[mb][h];
            s += __shfl_xor_sync(0xffffffffu, s, 1);
            s += __shfl_xor_sync(0xffffffffu, s, 2);
            lp[mb][h] = s;
        }
    if (tig == 0)
        #pragma unroll
        for (int mb = 0; mb < 2; mb++)
            #pragma unroll
            for (int h = 0; h < 2; h++)
                red[(wm * 32 + mb * 16 + g + h * 8) * 2 + wn] = lp[mb][h];
    __syncthreads();
    if (tid < MT) {
        float li = 1.f / (red[tid * 2] + red[tid * 2 + 1]);
        liS[tid] = li;
        g_linv[(size_t)bh * S_LEN + q0 + tid] = li;
    }
    __syncthreads();

    // ---- write context ----
    #pragma unroll
    for (int mb = 0; mb < 2; mb++) {
        int row = wm * 32 + mb * 16 + g;
        float li0 = liS[row], li1 = liS[row + 8];
        #pragma unroll
        for (int nf = 0; nf < 4; nf++) {
            int col = wn * 32 + nf * 8 + 2 * tig;
            *(float2*)(ctx + (size_t)(q0 + row)     * D_K + col) =
                make_float2(o[mb][nf][0] * li0, o[mb][nf][1] * li0);
            *(float2*)(ctx + (size_t)(q0 + row + 8) * D_K + col) =
                make_float2(o[mb][nf][2] * li1, o[mb][nf][3] * li1);
        }
    }

    // ---- produce/consume: normalize one already-produced strip ----
    __threadfence();
    __syncthreads();
    if (tid == 0) {
        int idx = atomicAdd(&g_push, 1);
        asm volatile("st.release.gpu.global.s32 [%0], %1;"
                     :: "l"(g_queue + idx), "r"(myid) : "memory");
        int t = atomicAdd(&g_ticket, 1);
        int s;
        while (true) {
            asm volatile("ld.acquire.gpu.global.s32 %0, [%1];"
                         : "=r"(s) : "l"(g_queue + t) : "memory");
            if (s >= 0) break;
            __nanosleep(64);
        }
        s_strip = s;
    }
    __syncthreads();

    const int sid  = s_strip;
    const int sbh  = sid >> 4;                 // 16 strips per bh
    const int sq0  = (sid & 15) * MT;
    float* sattn = attn_base + (size_t)sbh * S_LEN * S_LEN + (size_t)sq0 * S_LEN;
    if (tid < MT) liS[tid] = g_linv[(size_t)sbh * S_LEN + sq0 + tid];
    __syncthreads();

    #pragma unroll 4
    for (int i = tid; i < MT * (S_LEN / 4); i += THREADS) {
        float li = liS[i >> 9];
        float4* p = (float4*)sattn + i;
        float4 v = *p;
        v.x *= li; v.y *= li; v.z *= li; v.w *= li;
        *p = v;
    }
}

extern "C" void kernel_launch(void* const* d_in, const int* in_sizes, int n_in,
                              void* d_out, int out_size) {
    const float* Q    = (const float*)d_in[0];
    const float* K    = (const float*)d_in[1];
    const float* V    = (const float*)d_in[2];
    const int*   mask = (const int*)d_in[3];
    float* out = (float*)d_out;

    void* addr;
    cudaGetSymbolAddress(&addr, g_queue);
    cudaMemsetAsync(addr, 0xFF, sizeof(int) * NBLOCKS);
    cudaGetSymbolAddress(&addr, g_push);
    cudaMemsetAsync(addr, 0, sizeof(int));
    cudaGetSymbolAddress(&addr, g_ticket);
    cudaMemsetAsync(addr, 0, sizeof(int));

    const int smem = (MT * PADK + NT * PADK + NT * PADV + MT * PADK + MT * 2 + MT) * sizeof(float);
    cudaFuncSetAttribute(sdpa_fused, cudaFuncAttributeMaxDynamicSharedMemorySize, smem);

    dim3 grid(S_LEN / MT, BH);   // (16, 64)
    sdpa_fused<<<grid, THREADS, smem>>>(Q, K, V, mask, out);
}